// round 5
// baseline (speedup 1.0000x reference)
#include <cuda_runtime.h>
#include <cstdint>

// Problem constants (fixed shapes from reference)
#define BB_   2
#define CC_   64
#define DD_   31
#define HW_   16384                 // H*W = 128*128
#define CS_   507904                // channel stride = D*H*W
#define TILE_P 128                  // positions per CTA tile
#define N_TILES (BB_ * DD_ * (HW_ / TILE_P))   // 7936
#define DTILES (DD_ * (HW_ / TILE_P))          // 3968
#define GRID_ 296                   // persistent: 2 CTAs/SM * 148 SMs
#define STRIDE_ 136                 // Hs row stride (floats): GEMM2 B-reads conflict-free

// SMEM layout (float offsets): w1[8192] | w2[4096] | b1[64] | b2[64] | Hs[64*136]
#define SM_W1 0
#define SM_W2 8192
#define SM_B1 12288
#define SM_B2 12352
#define SM_H  12416
#define SM_FLOATS (12416 + 64 * STRIDE_)   // 21120 floats = 84480 B (2 CTAs/SM: 169 KB)

__device__ __forceinline__ uint32_t f2tf(float f) {
    uint32_t u;
    asm("cvt.rna.tf32.f32 %0, %1;" : "=r"(u) : "f"(f));
    return u;
}
__device__ __forceinline__ float tanha(float v) {
    float r;
    asm("tanh.approx.f32 %0, %1;" : "=f"(r) : "f"(v));
    return r;
}
__device__ __forceinline__ void mma8(float& d0, float& d1, float& d2, float& d3,
                                     uint32_t a0, uint32_t a1, uint32_t a2, uint32_t a3,
                                     uint32_t b0, uint32_t b1) {
    asm("mma.sync.aligned.m16n8k8.row.col.f32.tf32.tf32.f32 "
        "{%0,%1,%2,%3}, {%4,%5,%6,%7}, {%8,%9}, {%0,%1,%2,%3};"
        : "+f"(d0), "+f"(d1), "+f"(d2), "+f"(d3)
        : "r"(a0), "r"(a1), "r"(a2), "r"(a3), "r"(b0), "r"(b1));
}

extern "C" __global__ void __launch_bounds__(256, 2)
ssaf_kernel(const float* __restrict__ x, const float* __restrict__ y,
            const float* __restrict__ w1, const float* __restrict__ b1,
            const float* __restrict__ w2, const float* __restrict__ b2,
            float* __restrict__ out)
{
    extern __shared__ float sm[];
    float* w1s = sm + SM_W1;
    float* w2s = sm + SM_W2;
    float* b1s = sm + SM_B1;
    float* b2s = sm + SM_B2;
    float* Hs  = sm + SM_H;

    const int tid  = threadIdx.x;
    const int wid  = tid >> 5;          // 0..7
    const int lane = tid & 31;
    const int t    = lane & 3;          // k index within fragment
    const int g    = lane >> 2;         // row/col index within fragment

    // ---- Load + tf32-convert weights into smem, pre-swizzled in A-fragment order ----
    // dest index i = ((kk*4 + mm)*32 + lane)*4 + j  ->  one LDS.128 per (kk,mm) per lane
    // frag regs: j=0:(g,t) j=1:(g+8,t) j=2:(g,t+4) j=3:(g+8,t+4)
    for (int i = tid; i < 8192; i += 256) {
        int kk = i >> 9; int rem = i & 511;
        int mm = rem >> 7; int l = (rem >> 2) & 31; int jj = rem & 3;
        int gg = l >> 2, tt = l & 3;
        int m = mm * 16 + gg + (jj & 1) * 8;
        int k = kk * 8 + tt + (jj >> 1) * 4;
        w1s[i] = __uint_as_float(f2tf(w1[m * 128 + k]));
    }
    for (int i = tid; i < 4096; i += 256) {
        int kk = i >> 9; int rem = i & 511;
        int mm = rem >> 7; int l = (rem >> 2) & 31; int jj = rem & 3;
        int gg = l >> 2, tt = l & 3;
        int m = mm * 16 + gg + (jj & 1) * 8;
        int k = kk * 8 + tt + (jj >> 1) * 4;
        w2s[i] = __uint_as_float(f2tf(w2[m * 64 + k]));
    }
    if (tid < 64) { b1s[tid] = b1[tid]; b2s[tid] = b2[tid]; }
    __syncthreads();

    const int wcol = wid * 16;          // warp's position offset within tile (16 positions)

    for (int tile = blockIdx.x; tile < N_TILES; tile += GRID_) {
        const int bb  = tile / DTILES;
        const int rem = tile - bb * DTILES;
        const int dd  = rem >> 7;
        const int hw0 = (rem & 127) << 7;
        const int p0  = hw0 + wcol;
        const size_t slabBase = ((size_t)(bb * CC_) * DD_ + dd) * (size_t)HW_;

        // B-operand pointer for concat-k-tile kk (k = kk*8 + t, +4*CS_ for the hi half)
        const float* xb = x + slabBase + (size_t)t * CS_ + p0 + g;
        const float* yb = y + slabBase + (size_t)t * CS_ + p0 + g;

        // ---------------- GEMM1: H = tanh(W1 * [x;y] + b1) ----------------
        float acc[4][2][4];
        #pragma unroll
        for (int mm = 0; mm < 4; mm++) {
            const float bv0 = b1s[mm * 16 + g];
            const float bv1 = b1s[mm * 16 + g + 8];
            #pragma unroll
            for (int nt = 0; nt < 2; nt++) {
                acc[mm][nt][0] = bv0; acc[mm][nt][1] = bv0;
                acc[mm][nt][2] = bv1; acc[mm][nt][3] = bv1;
            }
        }

        // software-pipelined over 16 k-tiles: raw loads one k-tile ahead
        float c0[2], c1[2], n0[2], n1[2];
        {
            const float* p = xb;                       // kk = 0
            c0[0] = p[0]; c0[1] = p[8];
            c1[0] = p[4 * CS_]; c1[1] = p[4 * CS_ + 8];
        }
        #pragma unroll
        for (int kk = 0; kk < 16; kk++) {
            if (kk < 15) {
                const int kn = kk + 1;
                const float* p = ((kn < 8) ? xb : yb) + (size_t)((kn & 7) * 8) * CS_;
                n0[0] = p[0]; n0[1] = p[8];
                n1[0] = p[4 * CS_]; n1[1] = p[4 * CS_ + 8];
            }
            const uint32_t bf0[2] = { f2tf(c0[0]), f2tf(c0[1]) };
            const uint32_t bf1[2] = { f2tf(c1[0]), f2tf(c1[1]) };
            #pragma unroll
            for (int mm = 0; mm < 4; mm++) {
                const uint4 a = *(const uint4*)(w1s + ((kk * 4 + mm) * 32 + lane) * 4);
                mma8(acc[mm][0][0], acc[mm][0][1], acc[mm][0][2], acc[mm][0][3],
                     a.x, a.y, a.z, a.w, bf0[0], bf1[0]);
                mma8(acc[mm][1][0], acc[mm][1][1], acc[mm][1][2], acc[mm][1][3],
                     a.x, a.y, a.z, a.w, bf0[1], bf1[1]);
            }
            c0[0] = n0[0]; c0[1] = n0[1]; c1[0] = n1[0]; c1[1] = n1[1];
        }

        // tanh -> store H to smem as tf32 bits (per-warp private columns)
        #pragma unroll
        for (int mm = 0; mm < 4; mm++) {
            const int r0 = mm * 16 + g;
            #pragma unroll
            for (int nt = 0; nt < 2; nt++) {
                const int col = wcol + nt * 8 + 2 * t;
                float2 h0, h1;
                h0.x = __uint_as_float(f2tf(tanha(acc[mm][nt][0])));
                h0.y = __uint_as_float(f2tf(tanha(acc[mm][nt][1])));
                h1.x = __uint_as_float(f2tf(tanha(acc[mm][nt][2])));
                h1.y = __uint_as_float(f2tf(tanha(acc[mm][nt][3])));
                *(float2*)(Hs + r0 * STRIDE_ + col)       = h0;
                *(float2*)(Hs + (r0 + 8) * STRIDE_ + col) = h1;
            }
        }
        __syncwarp();

        // ---------------- GEMM2: U = W2 * H + b2 ----------------
        float acc2[4][2][4];
        #pragma unroll
        for (int mm = 0; mm < 4; mm++) {
            const float bv0 = b2s[mm * 16 + g];
            const float bv1 = b2s[mm * 16 + g + 8];
            #pragma unroll
            for (int nt = 0; nt < 2; nt++) {
                acc2[mm][nt][0] = bv0; acc2[mm][nt][1] = bv0;
                acc2[mm][nt][2] = bv1; acc2[mm][nt][3] = bv1;
            }
        }
        #pragma unroll
        for (int kk = 0; kk < 8; kk++) {
            uint32_t bf0[2], bf1[2];
            #pragma unroll
            for (int nt = 0; nt < 2; nt++) {
                bf0[nt] = __float_as_uint(Hs[(kk * 8 + t) * STRIDE_ + wcol + nt * 8 + g]);
                bf1[nt] = __float_as_uint(Hs[(kk * 8 + t + 4) * STRIDE_ + wcol + nt * 8 + g]);
            }
            #pragma unroll
            for (int mm = 0; mm < 4; mm++) {
                const uint4 a = *(const uint4*)(w2s + ((kk * 4 + mm) * 32 + lane) * 4);
                mma8(acc2[mm][0][0], acc2[mm][0][1], acc2[mm][0][2], acc2[mm][0][3],
                     a.x, a.y, a.z, a.w, bf0[0], bf1[0]);
                mma8(acc2[mm][1][0], acc2[mm][1][1], acc2[mm][1][2], acc2[mm][1][3],
                     a.x, a.y, a.z, a.w, bf0[1], bf1[1]);
            }
        }

        // ---------------- Epilogue: out = x + sigmoid(U) * (y - x) ----------------
        // sigmoid(u) = 0.5 + 0.5*tanh(0.5*u); x,y re-reads are L2 hits.
        #pragma unroll
        for (int mm = 0; mm < 4; mm++) {
            #pragma unroll
            for (int nt = 0; nt < 2; nt++) {
                const int pcol = hw0 + wcol + nt * 8 + 2 * t;
                #pragma unroll
                for (int half = 0; half < 2; half++) {
                    const int r = mm * 16 + g + half * 8;
                    const size_t idx = slabBase + (size_t)r * CS_ + pcol;
                    const float u0 = acc2[mm][nt][half * 2 + 0];
                    const float u1 = acc2[mm][nt][half * 2 + 1];
                    const float g0 = 0.5f + 0.5f * tanha(0.5f * u0);
                    const float g1 = 0.5f + 0.5f * tanha(0.5f * u1);
                    const float2 xv = *(const float2*)(x + idx);
                    const float2 yv = *(const float2*)(y + idx);
                    float2 ov;
                    ov.x = fmaf(g0, yv.x - xv.x, xv.x);
                    ov.y = fmaf(g1, yv.y - xv.y, xv.y);
                    *(float2*)(out + idx) = ov;
                }
            }
        }
        // Hs columns are warp-private: no CTA barrier needed between tiles.
    }
}

extern "C" void kernel_launch(void* const* d_in, const int* in_sizes, int n_in,
                              void* d_out, int out_size)
{
    const float* x  = (const float*)d_in[0];
    const float* y  = (const float*)d_in[1];
    const float* w1 = (const float*)d_in[2];
    const float* b1 = (const float*)d_in[3];
    const float* w2 = (const float*)d_in[4];
    const float* b2 = (const float*)d_in[5];
    float* out = (float*)d_out;

    const int smem_bytes = SM_FLOATS * (int)sizeof(float);   // 84480 B
    cudaFuncSetAttribute(ssaf_kernel, cudaFuncAttributeMaxDynamicSharedMemorySize, smem_bytes);
    ssaf_kernel<<<GRID_, 256, smem_bytes>>>(x, y, w1, b1, w2, b2, out);
}

// round 8
// speedup vs baseline: 2.9468x; 2.9468x over previous
#include <cuda_runtime.h>
#include <cstdint>

// Problem constants (fixed shapes from reference)
#define BB_   2
#define CC_   64
#define DD_   31
#define HW_   16384                 // H*W = 128*128
#define CS_   507904                // channel stride = D*H*W
#define N_TILES 7936                // B * D * (HW/128)
#define DTILES  3968                // D * (HW/128)
#define GRID_ 296                   // persistent: 2 CTAs/SM * 148 SMs
#define SH_   136                   // H/gate smem row stride: GEMM2 frag reads bank 8t+g, conflict-free

// SMEM layout (floats): w1s[8192] | w2s[4096] | b1s[64] | b2s[64] | Rg[64*136]
#define SM_W1 0
#define SM_W2 8192
#define SM_B1 12288
#define SM_B2 12352
#define SM_R  12416
#define SM_FLOATS (12416 + 64 * SH_)        // 21120 floats = 84480 B (2 CTAs/SM fits)

__device__ __forceinline__ uint32_t f2tf(float f) {
    uint32_t u;
    asm("cvt.rna.tf32.f32 %0, %1;" : "=r"(u) : "f"(f));
    return u;
}
__device__ __forceinline__ float tanha(float v) {
    float r;
    asm("tanh.approx.f32 %0, %1;" : "=f"(r) : "f"(v));
    return r;
}
__device__ __forceinline__ void mma8(float& d0, float& d1, float& d2, float& d3,
                                     uint32_t a0, uint32_t a1, uint32_t a2, uint32_t a3,
                                     uint32_t b0, uint32_t b1) {
    asm("mma.sync.aligned.m16n8k8.row.col.f32.tf32.tf32.f32 "
        "{%0,%1,%2,%3}, {%4,%5,%6,%7}, {%8,%9}, {%0,%1,%2,%3};"
        : "+f"(d0), "+f"(d1), "+f"(d2), "+f"(d3)
        : "r"(a0), "r"(a1), "r"(a2), "r"(a3), "r"(b0), "r"(b1));
}

extern "C" __global__ void __launch_bounds__(128, 2)
ssaf_kernel(const float* __restrict__ x, const float* __restrict__ y,
            const float* __restrict__ w1, const float* __restrict__ b1,
            const float* __restrict__ w2, const float* __restrict__ b2,
            float* __restrict__ out)
{
    extern __shared__ float sm[];
    float* w1s = sm + SM_W1;
    float* w2s = sm + SM_W2;
    float* b1s = sm + SM_B1;
    float* b2s = sm + SM_B2;
    float* Rg  = sm + SM_R;      // holds H between GEMMs, then the gates for the epilogue

    const int tid  = threadIdx.x;
    const int wid  = tid >> 5;
    const int lane = tid & 31;
    const int t    = lane & 3;   // k index within fragment
    const int g    = lane >> 2;  // row/col index within fragment

    // ---- Load + tf32-convert weights into smem, pre-swizzled in A-fragment order ----
    // dest index i = ((kk*4 + mm)*32 + lane)*4 + j  ->  one LDS.128 per (kk,mm) per lane
    // frag regs: j=0:(g,t) j=1:(g+8,t) j=2:(g,t+4) j=3:(g+8,t+4)
    for (int i = tid; i < 8192; i += 128) {
        int kk = i >> 9; int rem = i & 511;
        int mm = rem >> 7; int l = (rem >> 2) & 31; int jj = rem & 3;
        int gg = l >> 2, tt = l & 3;
        int m = mm * 16 + gg + (jj & 1) * 8;
        int k = kk * 8 + tt + (jj >> 1) * 4;
        w1s[i] = __uint_as_float(f2tf(w1[m * 128 + k]));
    }
    for (int i = tid; i < 4096; i += 128) {
        int kk = i >> 9; int rem = i & 511;
        int mm = rem >> 7; int l = (rem >> 2) & 31; int jj = rem & 3;
        int gg = l >> 2, tt = l & 3;
        int m = mm * 16 + gg + (jj & 1) * 8;
        int k = kk * 8 + tt + (jj >> 1) * 4;
        w2s[i] = __uint_as_float(f2tf(w2[m * 64 + k]));
    }
    if (tid < 64) { b1s[tid] = b1[tid]; b2s[tid] = b2[tid]; }
    __syncthreads();

    const int wcol = wid * 32;   // warp's position slice within the 128-pos tile

    for (int tile = blockIdx.x; tile < N_TILES; tile += GRID_) {
        const int bb  = tile / DTILES;
        const int rem = tile - bb * DTILES;
        const int dd  = rem >> 7;
        const int hw0 = (rem & 127) << 7;
        const int p0  = hw0 + wcol;
        const size_t slabBase = ((size_t)(bb * CC_) * DD_ + dd) * (size_t)HW_;

        // ---------------- GEMM1: H = tanh(W1 * [x;y] + b1) ----------------
        float acc[4][4][4];
        #pragma unroll
        for (int mm = 0; mm < 4; mm++) {
            const float bv0 = b1s[mm * 16 + g];
            const float bv1 = b1s[mm * 16 + g + 8];
            #pragma unroll
            for (int nt = 0; nt < 4; nt++) {
                acc[mm][nt][0] = bv0; acc[mm][nt][1] = bv0;
                acc[mm][nt][2] = bv1; acc[mm][nt][3] = bv1;
            }
        }

        // x half: k-tiles 0..7 (concat channels 0..63)
        {
            const float* p_lo = x + slabBase + (size_t)t * CS_ + p0 + g;
            const float* p_hi = p_lo + (size_t)4 * CS_;
            #pragma unroll
            for (int kk = 0; kk < 8; kk++) {
                uint32_t bf0[4], bf1[4];
                #pragma unroll
                for (int nt = 0; nt < 4; nt++) {
                    bf0[nt] = f2tf(p_lo[nt * 8]);
                    bf1[nt] = f2tf(p_hi[nt * 8]);
                }
                #pragma unroll
                for (int mm = 0; mm < 4; mm++) {
                    const uint4 a = *(const uint4*)(w1s + ((kk * 4 + mm) * 32 + lane) * 4);
                    #pragma unroll
                    for (int nt = 0; nt < 4; nt++)
                        mma8(acc[mm][nt][0], acc[mm][nt][1], acc[mm][nt][2], acc[mm][nt][3],
                             a.x, a.y, a.z, a.w, bf0[nt], bf1[nt]);
                }
                p_lo += (size_t)8 * CS_;
                p_hi += (size_t)8 * CS_;
            }
        }
        // y half: k-tiles 8..15 (concat channels 64..127)
        {
            const float* p_lo = y + slabBase + (size_t)t * CS_ + p0 + g;
            const float* p_hi = p_lo + (size_t)4 * CS_;
            #pragma unroll
            for (int kk = 8; kk < 16; kk++) {
                uint32_t bf0[4], bf1[4];
                #pragma unroll
                for (int nt = 0; nt < 4; nt++) {
                    bf0[nt] = f2tf(p_lo[nt * 8]);
                    bf1[nt] = f2tf(p_hi[nt * 8]);
                }
                #pragma unroll
                for (int mm = 0; mm < 4; mm++) {
                    const uint4 a = *(const uint4*)(w1s + ((kk * 4 + mm) * 32 + lane) * 4);
                    #pragma unroll
                    for (int nt = 0; nt < 4; nt++)
                        mma8(acc[mm][nt][0], acc[mm][nt][1], acc[mm][nt][2], acc[mm][nt][3],
                             a.x, a.y, a.z, a.w, bf0[nt], bf1[nt]);
                }
                p_lo += (size_t)8 * CS_;
                p_hi += (size_t)8 * CS_;
            }
        }

        // tanh -> store H (tf32 bits) to Rg; columns wcol..wcol+31 are warp-private
        #pragma unroll
        for (int mm = 0; mm < 4; mm++) {
            const int r0 = mm * 16 + g;
            #pragma unroll
            for (int nt = 0; nt < 4; nt++) {
                const int col = wcol + nt * 8 + 2 * t;
                float2 h0, h1;
                h0.x = __uint_as_float(f2tf(tanha(acc[mm][nt][0])));
                h0.y = __uint_as_float(f2tf(tanha(acc[mm][nt][1])));
                h1.x = __uint_as_float(f2tf(tanha(acc[mm][nt][2])));
                h1.y = __uint_as_float(f2tf(tanha(acc[mm][nt][3])));
                *(float2*)(Rg + r0 * SH_ + col)       = h0;
                *(float2*)(Rg + (r0 + 8) * SH_ + col) = h1;
            }
        }
        __syncwarp();

        // ---------------- GEMM2: U = W2 * H + b2 ----------------
        float acc2[4][4][4];
        #pragma unroll
        for (int mm = 0; mm < 4; mm++) {
            const float bv0 = b2s[mm * 16 + g];
            const float bv1 = b2s[mm * 16 + g + 8];
            #pragma unroll
            for (int nt = 0; nt < 4; nt++) {
                acc2[mm][nt][0] = bv0; acc2[mm][nt][1] = bv0;
                acc2[mm][nt][2] = bv1; acc2[mm][nt][3] = bv1;
            }
        }
        #pragma unroll
        for (int kk = 0; kk < 8; kk++) {
            uint32_t bf0[4], bf1[4];
            #pragma unroll
            for (int nt = 0; nt < 4; nt++) {
                bf0[nt] = __float_as_uint(Rg[(kk * 8 + t) * SH_ + wcol + nt * 8 + g]);
                bf1[nt] = __float_as_uint(Rg[(kk * 8 + t + 4) * SH_ + wcol + nt * 8 + g]);
            }
            #pragma unroll
            for (int mm = 0; mm < 4; mm++) {
                const uint4 a = *(const uint4*)(w2s + ((kk * 4 + mm) * 32 + lane) * 4);
                #pragma unroll
                for (int nt = 0; nt < 4; nt++)
                    mma8(acc2[mm][nt][0], acc2[mm][nt][1], acc2[mm][nt][2], acc2[mm][nt][3],
                         a.x, a.y, a.z, a.w, bf0[nt], bf1[nt]);
            }
        }
        __syncwarp();   // all lanes done reading H before gates overwrite the region

        // ---------------- Gates -> Rg: sigmoid(u) = 0.5 + 0.5*tanh(0.5u) ----------------
        #pragma unroll
        for (int mm = 0; mm < 4; mm++) {
            #pragma unroll
            for (int nt = 0; nt < 4; nt++) {
                const int col = wcol + nt * 8 + 2 * t;
                #pragma unroll
                for (int half = 0; half < 2; half++) {
                    const int r = mm * 16 + g + half * 8;
                    float2 gv;
                    gv.x = 0.5f + 0.5f * tanha(0.5f * acc2[mm][nt][half * 2 + 0]);
                    gv.y = 0.5f + 0.5f * tanha(0.5f * acc2[mm][nt][half * 2 + 1]);
                    *(float2*)(Rg + r * SH_ + col) = gv;
                }
            }
        }
        __syncwarp();

        // ---------------- Epilogue: full-128B-line float4 r/w over warp's 32 positions ----------------
        // lane l handles channel r = 4i + (l>>3), positions wcol + (l&7)*4 .. +3
        #pragma unroll 4
        for (int i = 0; i < 16; i++) {
            const int r  = 4 * i + (lane >> 3);
            const int q4 = (lane & 7) * 4;
            const float4 gv = *(const float4*)(Rg + r * SH_ + wcol + q4);
            const size_t gi = slabBase + (size_t)r * CS_ + hw0 + wcol + q4;
            const float4 xv = *(const float4*)(x + gi);
            const float4 yv = *(const float4*)(y + gi);
            float4 ov;
            ov.x = fmaf(gv.x, yv.x - xv.x, xv.x);
            ov.y = fmaf(gv.y, yv.y - xv.y, xv.y);
            ov.z = fmaf(gv.z, yv.z - xv.z, xv.z);
            ov.w = fmaf(gv.w, yv.w - xv.w, xv.w);
            *(float4*)(out + gi) = ov;
        }
        __syncwarp();   // gate reads done before next tile's tanh stores overwrite Rg
    }
}

extern "C" void kernel_launch(void* const* d_in, const int* in_sizes, int n_in,
                              void* d_out, int out_size)
{
    const float* x  = (const float*)d_in[0];
    const float* y  = (const float*)d_in[1];
    const float* w1 = (const float*)d_in[2];
    const float* b1 = (const float*)d_in[3];
    const float* w2 = (const float*)d_in[4];
    const float* b2 = (const float*)d_in[5];
    float* out = (float*)d_out;

    const int smem_bytes = SM_FLOATS * (int)sizeof(float);   // 84480 B
    cudaFuncSetAttribute(ssaf_kernel, cudaFuncAttributeMaxDynamicSharedMemorySize, smem_bytes);
    ssaf_kernel<<<GRID_, 128, smem_bytes>>>(x, y, w1, b1, w2, b2, out);
}

// round 9
// speedup vs baseline: 2.9471x; 1.0001x over previous
#include <cuda_runtime.h>
#include <cstdint>

// Problem constants (fixed shapes from reference)
#define BB_   2
#define CC_   64
#define DD_   31
#define HW_   16384                 // H*W = 128*128
#define CS_   507904                // channel stride = D*H*W
#define N_TILES 7936                // B * D * (HW/128)
#define DTILES  3968                // D * (HW/128)
#define GRID_ 296                   // persistent: 2 CTAs/SM * 148 SMs
#define SH_   136                   // H/gate smem row stride: GEMM2 frag reads bank 8t+g, conflict-free

// SMEM layout (floats): w1s[8192] | w2s[4096] | b1s[64] | b2s[64] | Rg[64*136]
#define SM_W1 0
#define SM_W2 8192
#define SM_B1 12288
#define SM_B2 12352
#define SM_R  12416
#define SM_FLOATS (12416 + 64 * SH_)        // 21120 floats = 84480 B (2 CTAs/SM fits)

__device__ __forceinline__ uint32_t f2tf(float f) {
    uint32_t u;
    asm("cvt.rna.tf32.f32 %0, %1;" : "=r"(u) : "f"(f));
    return u;
}
__device__ __forceinline__ float tanha(float v) {
    float r;
    asm("tanh.approx.f32 %0, %1;" : "=f"(r) : "f"(v));
    return r;
}
__device__ __forceinline__ void mma8(float& d0, float& d1, float& d2, float& d3,
                                     uint32_t a0, uint32_t a1, uint32_t a2, uint32_t a3,
                                     uint32_t b0, uint32_t b1) {
    asm("mma.sync.aligned.m16n8k8.row.col.f32.tf32.tf32.f32 "
        "{%0,%1,%2,%3}, {%4,%5,%6,%7}, {%8,%9}, {%0,%1,%2,%3};"
        : "+f"(d0), "+f"(d1), "+f"(d2), "+f"(d3)
        : "r"(a0), "r"(a1), "r"(a2), "r"(a3), "r"(b0), "r"(b1));
}

extern "C" __global__ void __launch_bounds__(128, 2)
ssaf_kernel(const float* __restrict__ x, const float* __restrict__ y,
            const float* __restrict__ w1, const float* __restrict__ b1,
            const float* __restrict__ w2, const float* __restrict__ b2,
            float* __restrict__ out)
{
    extern __shared__ float sm[];
    float* w1s = sm + SM_W1;
    float* w2s = sm + SM_W2;
    float* b1s = sm + SM_B1;
    float* b2s = sm + SM_B2;
    float* Rg  = sm + SM_R;      // holds H between GEMMs, then the gates for the epilogue

    const int tid  = threadIdx.x;
    const int wid  = tid >> 5;
    const int lane = tid & 31;
    const int t    = lane & 3;   // k index within fragment
    const int g    = lane >> 2;  // row/col index within fragment

    // ---- Load + tf32-convert weights into smem, pre-swizzled in A-fragment order ----
    // dest index i = ((kk*4 + mm)*32 + lane)*4 + j  ->  one LDS.128 per (kk,mm) per lane
    // frag regs: j=0:(g,t) j=1:(g+8,t) j=2:(g,t+4) j=3:(g+8,t+4)
    for (int i = tid; i < 8192; i += 128) {
        int kk = i >> 9; int rem = i & 511;
        int mm = rem >> 7; int l = (rem >> 2) & 31; int jj = rem & 3;
        int gg = l >> 2, tt = l & 3;
        int m = mm * 16 + gg + (jj & 1) * 8;
        int k = kk * 8 + tt + (jj >> 1) * 4;
        w1s[i] = __uint_as_float(f2tf(w1[m * 128 + k]));
    }
    for (int i = tid; i < 4096; i += 128) {
        int kk = i >> 9; int rem = i & 511;
        int mm = rem >> 7; int l = (rem >> 2) & 31; int jj = rem & 3;
        int gg = l >> 2, tt = l & 3;
        int m = mm * 16 + gg + (jj & 1) * 8;
        int k = kk * 8 + tt + (jj >> 1) * 4;
        w2s[i] = __uint_as_float(f2tf(w2[m * 64 + k]));
    }
    if (tid < 64) { b1s[tid] = b1[tid]; b2s[tid] = b2[tid]; }
    __syncthreads();

    const int wcol = wid * 32;   // warp's position slice within the 128-pos tile

    for (int tile = blockIdx.x; tile < N_TILES; tile += GRID_) {
        const int bb  = tile / DTILES;
        const int rem = tile - bb * DTILES;
        const int dd  = rem >> 7;
        const int hw0 = (rem & 127) << 7;
        const int p0  = hw0 + wcol;
        const size_t slabBase = ((size_t)(bb * CC_) * DD_ + dd) * (size_t)HW_;

        // ---------------- GEMM1: H = tanh(W1 * [x;y] + b1) ----------------
        float acc[4][4][4];
        #pragma unroll
        for (int mm = 0; mm < 4; mm++) {
            const float bv0 = b1s[mm * 16 + g];
            const float bv1 = b1s[mm * 16 + g + 8];
            #pragma unroll
            for (int nt = 0; nt < 4; nt++) {
                acc[mm][nt][0] = bv0; acc[mm][nt][1] = bv0;
                acc[mm][nt][2] = bv1; acc[mm][nt][3] = bv1;
            }
        }

        // B-operand bases: concat k-tile j lives at ((j<8)?x:y) + (j&7)*8*CS_
        const float* xb = x + slabBase + (size_t)t * CS_ + p0 + g;
        const float* yb = y + slabBase + (size_t)t * CS_ + p0 + g;

        auto loadkt = [&](float* lo, float* hi, int j) {
            const float* p = ((j < 8) ? xb : yb) + (size_t)((j & 7) * 8) * CS_;
            #pragma unroll
            for (int nt = 0; nt < 4; nt++) {
                lo[nt] = p[nt * 8];
                hi[nt] = p[(size_t)4 * CS_ + nt * 8];
            }
        };

        // depth-2 software pipeline over the 16 concat k-tiles
        float bl[3][4], bh[3][4];
        loadkt(bl[0], bh[0], 0);
        loadkt(bl[1], bh[1], 1);
        #pragma unroll
        for (int kk = 0; kk < 16; kk++) {
            if (kk + 2 < 16)
                loadkt(bl[(kk + 2) % 3], bh[(kk + 2) % 3], kk + 2);
            uint32_t bf0[4], bf1[4];
            #pragma unroll
            for (int nt = 0; nt < 4; nt++) {
                bf0[nt] = f2tf(bl[kk % 3][nt]);
                bf1[nt] = f2tf(bh[kk % 3][nt]);
            }
            #pragma unroll
            for (int mm = 0; mm < 4; mm++) {
                const uint4 a = *(const uint4*)(w1s + ((kk * 4 + mm) * 32 + lane) * 4);
                #pragma unroll
                for (int nt = 0; nt < 4; nt++)
                    mma8(acc[mm][nt][0], acc[mm][nt][1], acc[mm][nt][2], acc[mm][nt][3],
                         a.x, a.y, a.z, a.w, bf0[nt], bf1[nt]);
            }
        }

        // tanh -> store H (tf32 bits) to Rg; columns wcol..wcol+31 are warp-private
        #pragma unroll
        for (int mm = 0; mm < 4; mm++) {
            const int r0 = mm * 16 + g;
            #pragma unroll
            for (int nt = 0; nt < 4; nt++) {
                const int col = wcol + nt * 8 + 2 * t;
                float2 h0, h1;
                h0.x = __uint_as_float(f2tf(tanha(acc[mm][nt][0])));
                h0.y = __uint_as_float(f2tf(tanha(acc[mm][nt][1])));
                h1.x = __uint_as_float(f2tf(tanha(acc[mm][nt][2])));
                h1.y = __uint_as_float(f2tf(tanha(acc[mm][nt][3])));
                *(float2*)(Rg + r0 * SH_ + col)       = h0;
                *(float2*)(Rg + (r0 + 8) * SH_ + col) = h1;
            }
        }
        __syncwarp();

        // ---------------- GEMM2: U = W2 * H + b2 ----------------
        float acc2[4][4][4];
        #pragma unroll
        for (int mm = 0; mm < 4; mm++) {
            const float bv0 = b2s[mm * 16 + g];
            const float bv1 = b2s[mm * 16 + g + 8];
            #pragma unroll
            for (int nt = 0; nt < 4; nt++) {
                acc2[mm][nt][0] = bv0; acc2[mm][nt][1] = bv0;
                acc2[mm][nt][2] = bv1; acc2[mm][nt][3] = bv1;
            }
        }
        #pragma unroll
        for (int kk = 0; kk < 8; kk++) {
            uint32_t bf0[4], bf1[4];
            #pragma unroll
            for (int nt = 0; nt < 4; nt++) {
                bf0[nt] = __float_as_uint(Rg[(kk * 8 + t) * SH_ + wcol + nt * 8 + g]);
                bf1[nt] = __float_as_uint(Rg[(kk * 8 + t + 4) * SH_ + wcol + nt * 8 + g]);
            }
            #pragma unroll
            for (int mm = 0; mm < 4; mm++) {
                const uint4 a = *(const uint4*)(w2s + ((kk * 4 + mm) * 32 + lane) * 4);
                #pragma unroll
                for (int nt = 0; nt < 4; nt++)
                    mma8(acc2[mm][nt][0], acc2[mm][nt][1], acc2[mm][nt][2], acc2[mm][nt][3],
                         a.x, a.y, a.z, a.w, bf0[nt], bf1[nt]);
            }
        }
        __syncwarp();   // all lanes done reading H before gates overwrite the region

        // ---------------- Gates -> Rg: sigmoid(u) = 0.5 + 0.5*tanh(0.5u) ----------------
        #pragma unroll
        for (int mm = 0; mm < 4; mm++) {
            #pragma unroll
            for (int nt = 0; nt < 4; nt++) {
                const int col = wcol + nt * 8 + 2 * t;
                #pragma unroll
                for (int half = 0; half < 2; half++) {
                    const int r = mm * 16 + g + half * 8;
                    float2 gv;
                    gv.x = 0.5f + 0.5f * tanha(0.5f * acc2[mm][nt][half * 2 + 0]);
                    gv.y = 0.5f + 0.5f * tanha(0.5f * acc2[mm][nt][half * 2 + 1]);
                    *(float2*)(Rg + r * SH_ + col) = gv;
                }
            }
        }
        __syncwarp();

        // ---------------- Epilogue: full-128B-line float4 r/w over warp's 32 positions ----------------
        // lane l handles channel r = 4i + (l>>3), positions wcol + (l&7)*4 .. +3
        #pragma unroll 4
        for (int i = 0; i < 16; i++) {
            const int r  = 4 * i + (lane >> 3);
            const int q4 = (lane & 7) * 4;
            const float4 gv = *(const float4*)(Rg + r * SH_ + wcol + q4);
            const size_t gi = slabBase + (size_t)r * CS_ + hw0 + wcol + q4;
            const float4 xv = *(const float4*)(x + gi);
            const float4 yv = *(const float4*)(y + gi);
            float4 ov;
            ov.x = fmaf(gv.x, yv.x - xv.x, xv.x);
            ov.y = fmaf(gv.y, yv.y - xv.y, xv.y);
            ov.z = fmaf(gv.z, yv.z - xv.z, xv.z);
            ov.w = fmaf(gv.w, yv.w - xv.w, xv.w);
            *(float4*)(out + gi) = ov;
        }
        __syncwarp();   // gate reads done before next tile's tanh stores overwrite Rg
    }
}

extern "C" void kernel_launch(void* const* d_in, const int* in_sizes, int n_in,
                              void* d_out, int out_size)
{
    const float* x  = (const float*)d_in[0];
    const float* y  = (const float*)d_in[1];
    const float* w1 = (const float*)d_in[2];
    const float* b1 = (const float*)d_in[3];
    const float* w2 = (const float*)d_in[4];
    const float* b2 = (const float*)d_in[5];
    float* out = (float*)d_out;

    const int smem_bytes = SM_FLOATS * (int)sizeof(float);   // 84480 B
    cudaFuncSetAttribute(ssaf_kernel, cudaFuncAttributeMaxDynamicSharedMemorySize, smem_bytes);
    ssaf_kernel<<<GRID_, 128, smem_bytes>>>(x, y, w1, b1, w2, b2, out);
}